// round 6
// baseline (speedup 1.0000x reference)
#include <cuda_runtime.h>
#include <cstdint>
#include <math.h>

#define NB 8
#define NC 256
#define NL 2048
#define BM 128
#define BN 128
#define BK 32
#define NTHREADS 256
#define NSTAGE 3
#define L2E 1.4426950408889634f

// smem geometry (floats): row stride 36 (32 data + 4 pad)
#define RS 36
#define TBUF (128 * RS)                    // 4608 floats per operand tile
#define SMEM_FLOATS (NSTAGE * 2 * TBUF)    // 27648 floats = 110592 B

// ---------------- scratch ----------------
__device__ float  g_Qt[NB * NL * NC];   // [b][l][c] (scaled + tf32-rounded)
__device__ float  g_Kt[NB * NL * NC];   // [b][m][c] (tf32-rounded)
__device__ float  g_V [NB * NC * NL];   // [b][c][m] (tf32-rounded)
__device__ float  g_S [NB * NL * NL];   // raw scaled scores
__device__ float2 g_stat[NB * NL];      // per row: (-max*log2e, 1/sum)

// ---------------- helpers ----------------
__device__ __forceinline__ uint32_t smem_u32(const void* p) {
    uint32_t a;
    asm("{ .reg .u64 t; cvta.to.shared.u64 t, %1; cvt.u32.u64 %0, t; }"
        : "=r"(a) : "l"(p));
    return a;
}
__device__ __forceinline__ float rna_tf32(float x) {
    uint32_t u;
    asm("cvt.rna.tf32.f32 %0, %1;" : "=r"(u) : "f"(x));
    return __uint_as_float(u);
}
__device__ __forceinline__ uint32_t rna_tf32_u(uint32_t x) {
    uint32_t u;
    asm("cvt.rna.tf32.f32 %0, %1;" : "=r"(u) : "f"(__uint_as_float(x)));
    return u;
}
__device__ __forceinline__ float ex2(float x) {
    float r;
    asm("ex2.approx.f32 %0, %1;" : "=f"(r) : "f"(x));
    return r;
}
__device__ __forceinline__ void cp_async16(uint32_t dst, const void* src) {
    asm volatile("cp.async.cg.shared.global [%0], [%1], 16;" :: "r"(dst), "l"(src));
}
__device__ __forceinline__ void ldsm4(uint32_t& r0, uint32_t& r1, uint32_t& r2,
                                      uint32_t& r3, uint32_t addr) {
    asm volatile("ldmatrix.sync.aligned.m8n8.x4.shared.b16 {%0,%1,%2,%3}, [%4];"
                 : "=r"(r0), "=r"(r1), "=r"(r2), "=r"(r3) : "r"(addr));
}
__device__ __forceinline__ void mma_tf32(float& d0, float& d1, float& d2, float& d3,
                                         uint32_t a0, uint32_t a1, uint32_t a2, uint32_t a3,
                                         uint32_t b0, uint32_t b1) {
    asm volatile(
        "mma.sync.aligned.m16n8k8.row.col.f32.tf32.tf32.f32 "
        "{%0,%1,%2,%3}, {%4,%5,%6,%7}, {%8,%9}, {%0,%1,%2,%3};"
        : "+f"(d0), "+f"(d1), "+f"(d2), "+f"(d3)
        : "r"(a0), "r"(a1), "r"(a2), "r"(a3), "r"(b0), "r"(b1));
}

// Shared mainloop.
// ROUND_FRAG: rna_tf32 on all fragments (raw fp32 inputs).
// EXPB: B holds raw scores; apply p = rna(ex2(fma(s,L2E,st.x)) * st.y) per frag.
//       st[ntp][hi] supplied by caller (per-thread row stats).
template <int ROUND_FRAG, int EXPB>
__device__ __forceinline__ void gemm_mainloop(
    const float* __restrict__ A, const float* __restrict__ B,
    int K, int ldA, int ldB, int r0, int c0,
    float* smem, int tid, int wm, int wn, int lane,
    float acc[4][4][4], const float2 st[2][2])
{
    const uint32_t sbase = smem_u32(smem);
    const int nchunks = K / BK;

    const int lrow = tid >> 3;
    const int lc4  = (tid & 7) * 4;

    const int aRow = wm + (lane & 15);
    const int aCol = (lane >> 4) * 4;
    const int bRow = wn + ((lane >> 4) & 1) * 8 + (lane & 7);
    const int bCol = ((lane >> 3) & 1) * 4;

    auto load_chunk = [&](int i) {
        const int s = i % NSTAGE;
        const uint32_t dA = sbase + (uint32_t)(s * 2 * TBUF) * 4u;
        const uint32_t dB = dA + (uint32_t)TBUF * 4u;
        const float* Ab = A + (size_t)r0 * ldA + (size_t)i * BK;
        const float* Bb = B + (size_t)c0 * ldB + (size_t)i * BK;
#pragma unroll
        for (int p = 0; p < 4; p++) {
            const int row = lrow + p * 32;
            cp_async16(dA + (uint32_t)(row * RS + lc4) * 4u, Ab + (size_t)row * ldA + lc4);
            cp_async16(dB + (uint32_t)(row * RS + lc4) * 4u, Bb + (size_t)row * ldB + lc4);
        }
    };

    load_chunk(0);
    asm volatile("cp.async.commit_group;");
    if (nchunks > 1) load_chunk(1);
    asm volatile("cp.async.commit_group;");

    for (int j = 0; j < nchunks; j++) {
        asm volatile("cp.async.wait_group 1;");
        __syncthreads();
        if (j + 2 < nchunks) load_chunk(j + 2);
        asm volatile("cp.async.commit_group;");

        const int s = j % NSTAGE;
        const uint32_t sA = sbase + (uint32_t)(s * 2 * TBUF) * 4u;
        const uint32_t sB = sA + (uint32_t)TBUF * 4u;
        const uint32_t aBase = sA + (uint32_t)(aRow * RS + aCol) * 4u;
        const uint32_t bBase = sB + (uint32_t)(bRow * RS + bCol) * 4u;

#pragma unroll
        for (int k8 = 0; k8 < 4; k8++) {
            const int kb = k8 * 8;
            uint32_t a[4][4], b[2][4];
#pragma unroll
            for (int mt = 0; mt < 4; mt++)
                ldsm4(a[mt][0], a[mt][1], a[mt][2], a[mt][3],
                      aBase + (uint32_t)((mt * 16) * RS + kb) * 4u);
#pragma unroll
            for (int ntp = 0; ntp < 2; ntp++)
                ldsm4(b[ntp][0], b[ntp][1], b[ntp][2], b[ntp][3],
                      bBase + (uint32_t)((ntp * 16) * RS + kb) * 4u);
            if (ROUND_FRAG) {
#pragma unroll
                for (int mt = 0; mt < 4; mt++)
#pragma unroll
                    for (int r = 0; r < 4; r++) a[mt][r] = rna_tf32_u(a[mt][r]);
#pragma unroll
                for (int ntp = 0; ntp < 2; ntp++)
#pragma unroll
                    for (int r = 0; r < 4; r++) b[ntp][r] = rna_tf32_u(b[ntp][r]);
            }
            if (EXPB) {
#pragma unroll
                for (int ntp = 0; ntp < 2; ntp++)
#pragma unroll
                    for (int r = 0; r < 4; r++) {
                        const float2 s2 = st[ntp][r >> 1];
                        float sv = __uint_as_float(b[ntp][r]);
                        float e = ex2(fmaf(sv, L2E, s2.x)) * s2.y;
                        b[ntp][r] = __float_as_uint(rna_tf32(e));
                    }
            }
#pragma unroll
            for (int mt = 0; mt < 4; mt++)
#pragma unroll
                for (int nt = 0; nt < 4; nt++)
                    mma_tf32(acc[mt][nt][0], acc[mt][nt][1], acc[mt][nt][2], acc[mt][nt][3],
                             a[mt][0], a[mt][1], a[mt][2], a[mt][3],
                             b[nt >> 1][(nt & 1) * 2], b[nt >> 1][(nt & 1) * 2 + 1]);
        }
    }
}

// ---------------------------------------------------------------------------
// Merged QKV projection GEMM (cols 0..2047 -> Q transposed+scaled,
// 2048..4095 -> K transposed, 4096..6143 -> V plain).
// ---------------------------------------------------------------------------
__global__ __launch_bounds__(NTHREADS, 2)
void qkv_gemm(const float* __restrict__ x,
              const float* __restrict__ Wq, const float* __restrict__ bq,
              const float* __restrict__ Wk, const float* __restrict__ bk,
              const float* __restrict__ Wv, const float* __restrict__ bv)
{
    extern __shared__ float smem[];

    const int tid = threadIdx.x;
    const int wid = tid >> 5;
    const int lane = tid & 31;
    const int g = lane >> 2;
    const int t = lane & 3;
    const int wm = (wid & 1) * 64;
    const int wn = (wid >> 1) * 32;

    const int r0 = blockIdx.y * BM;
    const int gc0 = blockIdx.x * BN;
    const int widx = gc0 >> 11;
    const int c0 = gc0 & (NL - 1);

    const float* W    = (widx == 0) ? Wq : (widx == 1) ? Wk : Wv;
    const float* bias = (widx == 0) ? bq : (widx == 1) ? bk : bv;
    const float scale = (widx == 0) ? 0.022097086912079612f : 1.0f;

    float acc[4][4][4];
#pragma unroll
    for (int i = 0; i < 4; i++)
#pragma unroll
        for (int j = 0; j < 4; j++)
#pragma unroll
            for (int k = 0; k < 4; k++) acc[i][j][k] = 0.0f;

    float2 stdummy[2][2];
    gemm_mainloop<1, 0>(x, W, NL, NL, NL, r0, c0, smem, tid, wm, wn, lane, acc, stdummy);

    const int bb  = r0 >> 8;
    const int cl0 = r0 & (NC - 1);

    if (widx < 2) {
        float* Tb = ((widx == 0) ? g_Qt : g_Kt) + (size_t)bb * NL * NC;
#pragma unroll
        for (int mt = 0; mt < 4; mt++) {
            const int cA = cl0 + wm + mt * 16 + g;
#pragma unroll
            for (int nt = 0; nt < 4; nt++) {
                const int l0 = c0 + wn + nt * 8 + 2 * t;
                const float b0 = bias[l0], b1 = bias[l0 + 1];
                Tb[(size_t)l0 * NC + cA]           = rna_tf32((acc[mt][nt][0] + b0) * scale);
                Tb[(size_t)(l0 + 1) * NC + cA]     = rna_tf32((acc[mt][nt][1] + b1) * scale);
                Tb[(size_t)l0 * NC + cA + 8]       = rna_tf32((acc[mt][nt][2] + b0) * scale);
                Tb[(size_t)(l0 + 1) * NC + cA + 8] = rna_tf32((acc[mt][nt][3] + b1) * scale);
            }
        }
    } else {
#pragma unroll
        for (int mt = 0; mt < 4; mt++) {
            const int row = r0 + wm + mt * 16 + g;
#pragma unroll
            for (int nt = 0; nt < 4; nt++) {
                const int col = c0 + wn + nt * 8 + 2 * t;
                const float b0 = bias[col], b1 = bias[col + 1];
                float v0 = rna_tf32(acc[mt][nt][0] + b0);
                float v1 = rna_tf32(acc[mt][nt][1] + b1);
                float v2 = rna_tf32(acc[mt][nt][2] + b0);
                float v3 = rna_tf32(acc[mt][nt][3] + b1);
                *(float2*)&g_V[(size_t)row * NL + col]       = make_float2(v0, v1);
                *(float2*)&g_V[(size_t)(row + 8) * NL + col] = make_float2(v2, v3);
            }
        }
    }
}

// ---------------------------------------------------------------------------
// Generic GEMM: C[M,N] = A[M,K] * B[N,K]^T, plain store.
// EXPB=1: B is raw scores; softmax applied on fragments via g_stat.
// ---------------------------------------------------------------------------
template <int EXPB>
__global__ __launch_bounds__(NTHREADS, 2)
void gemm0(const float* __restrict__ A, const float* __restrict__ B,
           float* __restrict__ C, int K, int ldA, int ldB, int ldC,
           size_t Az, size_t Bz, size_t Cz)
{
    extern __shared__ float smem[];

    const int tid = threadIdx.x;
    const int wid = tid >> 5;
    const int lane = tid & 31;
    const int g = lane >> 2;
    const int t = lane & 3;
    const int wm = (wid & 1) * 64;
    const int wn = (wid >> 1) * 32;

    const int z = blockIdx.z;
    A += (size_t)z * Az;
    B += (size_t)z * Bz;
    const int r0 = blockIdx.y * BM;
    const int c0 = blockIdx.x * BN;

    float2 st[2][2];
    if (EXPB) {
#pragma unroll
        for (int ntp = 0; ntp < 2; ntp++)
#pragma unroll
            for (int hi = 0; hi < 2; hi++)
                st[ntp][hi] = g_stat[(size_t)z * NL + c0 + wn + ntp * 16 + hi * 8 + g];
    }

    float acc[4][4][4];
#pragma unroll
    for (int i = 0; i < 4; i++)
#pragma unroll
        for (int j = 0; j < 4; j++)
#pragma unroll
            for (int k = 0; k < 4; k++) acc[i][j][k] = 0.0f;

    gemm_mainloop<0, EXPB>(A, B, K, ldA, ldB, r0, c0, smem, tid, wm, wn, lane, acc, st);

    float* Cb = C + (size_t)z * Cz;
#pragma unroll
    for (int mt = 0; mt < 4; mt++) {
        const int row = r0 + wm + mt * 16 + g;
#pragma unroll
        for (int nt = 0; nt < 4; nt++) {
            const int col = c0 + wn + nt * 8 + 2 * t;
            *(float2*)&Cb[(size_t)row * ldC + col] =
                make_float2(acc[mt][nt][0], acc[mt][nt][1]);
            *(float2*)&Cb[(size_t)(row + 8) * ldC + col] =
                make_float2(acc[mt][nt][2], acc[mt][nt][3]);
        }
    }
}

// ---------------------------------------------------------------------------
// Row stats: per (b,l) row of g_S compute (-max*log2e, 1/sum_exp).
// ---------------------------------------------------------------------------
__global__ void rowstat_kernel()
{
    const int row = blockIdx.x;
    const float* p = g_S + (size_t)row * NL;
    const int tid = threadIdx.x;

    float4 v[2];
    float m = -1e30f;
#pragma unroll
    for (int j = 0; j < 2; j++) {
        v[j] = *(const float4*)&p[(tid + j * 256) * 4];
        m = fmaxf(m, fmaxf(fmaxf(v[j].x, v[j].y), fmaxf(v[j].z, v[j].w)));
    }

    __shared__ float red[256];
    red[tid] = m;
    __syncthreads();
    for (int s = 128; s > 0; s >>= 1) {
        if (tid < s) red[tid] = fmaxf(red[tid], red[tid + s]);
        __syncthreads();
    }
    m = red[0];
    __syncthreads();

    const float mm = -m * L2E;
    float sum = 0.0f;
#pragma unroll
    for (int j = 0; j < 2; j++) {
        sum += ex2(fmaf(v[j].x, L2E, mm));
        sum += ex2(fmaf(v[j].y, L2E, mm));
        sum += ex2(fmaf(v[j].z, L2E, mm));
        sum += ex2(fmaf(v[j].w, L2E, mm));
    }
    red[tid] = sum;
    __syncthreads();
    for (int s = 128; s > 0; s >>= 1) {
        if (tid < s) red[tid] += red[tid + s];
        __syncthreads();
    }
    if (tid == 0)
        g_stat[row] = make_float2(mm, 1.0f / red[0]);
}

// ---------------------------------------------------------------------------
extern "C" void kernel_launch(void* const* d_in, const int* in_sizes, int n_in,
                              void* d_out, int out_size)
{
    const float* x  = (const float*)d_in[0];
    const float* Wq = (const float*)d_in[1];
    const float* bq = (const float*)d_in[2];
    const float* Wk = (const float*)d_in[3];
    const float* bk = (const float*)d_in[4];
    const float* Wv = (const float*)d_in[5];
    const float* bv = (const float*)d_in[6];
    float* out = (float*)d_out;

    float *Qt, *Kt, *V, *S;
    cudaGetSymbolAddress((void**)&Qt, g_Qt);
    cudaGetSymbolAddress((void**)&Kt, g_Kt);
    cudaGetSymbolAddress((void**)&V,  g_V);
    cudaGetSymbolAddress((void**)&S,  g_S);

    const int smem_bytes = SMEM_FLOATS * 4;  // 110592
    cudaFuncSetAttribute((const void*)qkv_gemm, cudaFuncAttributeMaxDynamicSharedMemorySize, smem_bytes);
    cudaFuncSetAttribute((const void*)gemm0<0>, cudaFuncAttributeMaxDynamicSharedMemorySize, smem_bytes);
    cudaFuncSetAttribute((const void*)gemm0<1>, cudaFuncAttributeMaxDynamicSharedMemorySize, smem_bytes);

    // 1) fused QKV projections
    qkv_gemm<<<dim3(3 * NL / BN, (NB * NC) / BM, 1), NTHREADS, smem_bytes>>>(
        x, Wq, bq, Wk, bk, Wv, bv);

    // 2) raw scaled scores: S[b][l][m] = Qt[b][l][:] . Kt[b][m][:]
    gemm0<0><<<dim3(NL / BN, NL / BM, NB), NTHREADS, smem_bytes>>>(
        Qt, Kt, S, NC, NC, NC, NL,
        (size_t)NL * NC, (size_t)NL * NC, (size_t)NL * NL);

    // 3) per-row softmax stats
    rowstat_kernel<<<NB * NL, 256>>>();

    // 4) out[b][c][l] = V[b][c][:] . softmax(S)[b][l][:]  (exp fused on frags)
    gemm0<1><<<dim3(NL / BN, NC / BM, NB), NTHREADS, smem_bytes>>>(
        V, S, out, NL, NL, NL, NL,
        (size_t)NC * NL, (size_t)NL * NL, (size_t)NC * NL);
}